// round 1
// baseline (speedup 1.0000x reference)
#include <cuda_runtime.h>

#define B_    16384
#define DIN_  1024
#define H_    512
#define DOUT_ 256
#define E_    8
#define NMID_ 2
#define EPS_  1e-5f

// ---------------- scratch (device globals: no allocs allowed) ----------------
__device__ float g_h[B_ * H_];          // activations ping
__device__ float g_y[B_ * H_];          // activations pong
__device__ float g_part_sum[32][H_];    // BN partial sums (deterministic 2-stage)
__device__ float g_part_sq[32][H_];
__device__ float g_scale[H_];
__device__ float g_shift[H_];
__device__ int   g_act[B_];
__device__ int   g_cnt[E_];
__device__ int   g_off[E_];
__device__ int   g_pos[E_];
__device__ int   g_perm[B_];

// ---------------- fused SGEMM: C = relu(A @ B + bias) ----------------
// A [M,K] row-major, B [K,N] row-major. BM=BN=128, BK=16, 8x8/thread, 256 thr.
// M % 128 == 0, N % 128 == 0, K % 16 == 0 (true for all call sites).
__global__ __launch_bounds__(256, 2)
void mlnn_sgemm_bias_relu(const float* __restrict__ A,
                          const float* __restrict__ Bw,
                          const float* __restrict__ bias,
                          float* __restrict__ C,
                          int N, int K)
{
    __shared__ float As[16][128];
    __shared__ float Bs[16][128];
    const int tid  = threadIdx.x;
    const int bm   = blockIdx.y * 128;
    const int bn   = blockIdx.x * 128;
    const int ar   = tid >> 2;           // 0..63
    const int ac   = (tid & 3) << 2;     // 0,4,8,12
    const int br   = tid >> 5;           // 0..7
    const int bc   = (tid & 31) << 2;    // 0..124
    const int trow = (tid >> 4) << 3;
    const int tcol = (tid & 15) << 3;

    const float* Ap0 = A + (size_t)(bm + ar) * K + ac;
    const float* Ap1 = Ap0 + (size_t)64 * K;

    float acc[8][8] = {};
    for (int k0 = 0; k0 < K; k0 += 16) {
        float4 a0 = *(const float4*)(Ap0 + k0);
        float4 a1 = *(const float4*)(Ap1 + k0);
        float4 b0 = *(const float4*)(Bw + (size_t)(k0 + br) * N + bn + bc);
        float4 b1 = *(const float4*)(Bw + (size_t)(k0 + br + 8) * N + bn + bc);
        __syncthreads();
        As[ac + 0][ar] = a0.x; As[ac + 1][ar] = a0.y;
        As[ac + 2][ar] = a0.z; As[ac + 3][ar] = a0.w;
        As[ac + 0][ar + 64] = a1.x; As[ac + 1][ar + 64] = a1.y;
        As[ac + 2][ar + 64] = a1.z; As[ac + 3][ar + 64] = a1.w;
        *(float4*)&Bs[br][bc]     = b0;
        *(float4*)&Bs[br + 8][bc] = b1;
        __syncthreads();
#pragma unroll
        for (int kk = 0; kk < 16; kk++) {
            float a[8], b[8];
            *(float4*)&a[0] = *(const float4*)&As[kk][trow];
            *(float4*)&a[4] = *(const float4*)&As[kk][trow + 4];
            *(float4*)&b[0] = *(const float4*)&Bs[kk][tcol];
            *(float4*)&b[4] = *(const float4*)&Bs[kk][tcol + 4];
#pragma unroll
            for (int i = 0; i < 8; i++)
#pragma unroll
                for (int j = 0; j < 8; j++)
                    acc[i][j] += a[i] * b[j];
        }
    }
#pragma unroll
    for (int i = 0; i < 8; i++) {
        const int row = bm + trow + i;
#pragma unroll
        for (int j = 0; j < 8; j += 4) {
            float4 v;
            v.x = fmaxf(acc[i][j + 0] + bias[bn + tcol + j + 0], 0.f);
            v.y = fmaxf(acc[i][j + 1] + bias[bn + tcol + j + 1], 0.f);
            v.z = fmaxf(acc[i][j + 2] + bias[bn + tcol + j + 2], 0.f);
            v.w = fmaxf(acc[i][j + 3] + bias[bn + tcol + j + 3], 0.f);
            *(float4*)&C[(size_t)row * N + bn + tcol + j] = v;
        }
    }
}

// ---------------- grouped expert SGEMM (gather rows by expert) ----------------
// y[perm[r],:] = relu(h[perm[r],:] @ We[e] + be[e]) for rows routed to e.
__global__ __launch_bounds__(256, 2)
void mlnn_expert_sgemm(const float* __restrict__ A,     // h_norm [B,H]
                       const float* __restrict__ WeL,   // [E,H,H]
                       const float* __restrict__ beL,   // [E,H]
                       float* __restrict__ C)           // y [B,H]
{
    const int e   = blockIdx.z;
    const int cnt = g_cnt[e];
    const int bm  = blockIdx.y * 128;
    if (bm >= cnt) return;
    const int base = g_off[e];
    const float* Bw   = WeL + (size_t)e * H_ * H_;
    const float* bias = beL + (size_t)e * H_;
    const int bn = blockIdx.x * 128;

    __shared__ float As[16][128];
    __shared__ float Bs[16][128];
    const int tid  = threadIdx.x;
    const int ar   = tid >> 2;
    const int ac   = (tid & 3) << 2;
    const int br   = tid >> 5;
    const int bc   = (tid & 31) << 2;
    const int trow = (tid >> 4) << 3;
    const int tcol = (tid & 15) << 3;

    const int r0 = bm + ar;
    const int r1 = bm + ar + 64;
    const float* Ap0 = (r0 < cnt) ? A + (size_t)g_perm[base + r0] * H_ + ac : nullptr;
    const float* Ap1 = (r1 < cnt) ? A + (size_t)g_perm[base + r1] * H_ + ac : nullptr;

    float acc[8][8] = {};
    for (int k0 = 0; k0 < H_; k0 += 16) {
        float4 a0 = Ap0 ? *(const float4*)(Ap0 + k0) : make_float4(0.f, 0.f, 0.f, 0.f);
        float4 a1 = Ap1 ? *(const float4*)(Ap1 + k0) : make_float4(0.f, 0.f, 0.f, 0.f);
        float4 b0 = *(const float4*)(Bw + (size_t)(k0 + br) * H_ + bn + bc);
        float4 b1 = *(const float4*)(Bw + (size_t)(k0 + br + 8) * H_ + bn + bc);
        __syncthreads();
        As[ac + 0][ar] = a0.x; As[ac + 1][ar] = a0.y;
        As[ac + 2][ar] = a0.z; As[ac + 3][ar] = a0.w;
        As[ac + 0][ar + 64] = a1.x; As[ac + 1][ar + 64] = a1.y;
        As[ac + 2][ar + 64] = a1.z; As[ac + 3][ar + 64] = a1.w;
        *(float4*)&Bs[br][bc]     = b0;
        *(float4*)&Bs[br + 8][bc] = b1;
        __syncthreads();
#pragma unroll
        for (int kk = 0; kk < 16; kk++) {
            float a[8], b[8];
            *(float4*)&a[0] = *(const float4*)&As[kk][trow];
            *(float4*)&a[4] = *(const float4*)&As[kk][trow + 4];
            *(float4*)&b[0] = *(const float4*)&Bs[kk][tcol];
            *(float4*)&b[4] = *(const float4*)&Bs[kk][tcol + 4];
#pragma unroll
            for (int i = 0; i < 8; i++)
#pragma unroll
                for (int j = 0; j < 8; j++)
                    acc[i][j] += a[i] * b[j];
        }
    }
#pragma unroll
    for (int i = 0; i < 8; i++) {
        const int rr = bm + trow + i;
        if (rr < cnt) {
            const int row = g_perm[base + rr];
#pragma unroll
            for (int j = 0; j < 8; j += 4) {
                float4 v;
                v.x = fmaxf(acc[i][j + 0] + bias[bn + tcol + j + 0], 0.f);
                v.y = fmaxf(acc[i][j + 1] + bias[bn + tcol + j + 1], 0.f);
                v.z = fmaxf(acc[i][j + 2] + bias[bn + tcol + j + 2], 0.f);
                v.w = fmaxf(acc[i][j + 3] + bias[bn + tcol + j + 3], 0.f);
                *(float4*)&C[(size_t)row * H_ + bn + tcol + j] = v;
            }
        }
    }
}

// ---------------- BN stats: deterministic two-stage column reduction ---------
__global__ void mlnn_bn_stats(const float* __restrict__ h)
{
    __shared__ float ss[8][33];
    __shared__ float sq[8][33];
    const int col = blockIdx.x * 32 + threadIdx.x;
    const int r0  = blockIdx.y * 512;
    float s = 0.f, q = 0.f;
    for (int i = threadIdx.y; i < 512; i += 8) {
        float v = h[(size_t)(r0 + i) * H_ + col];
        s += v; q += v * v;
    }
    ss[threadIdx.y][threadIdx.x] = s;
    sq[threadIdx.y][threadIdx.x] = q;
    __syncthreads();
    if (threadIdx.y == 0) {
#pragma unroll
        for (int y = 1; y < 8; y++) { s += ss[y][threadIdx.x]; q += sq[y][threadIdx.x]; }
        g_part_sum[blockIdx.y][col] = s;
        g_part_sq[blockIdx.y][col]  = q;
    }
}

// finalize: scale/shift per column; also zeroes expert counters for the
// routing pass that always follows in the launch sequence.
__global__ void mlnn_bn_finalize(const float* __restrict__ gamma,
                                 const float* __restrict__ beta)
{
    const int c = blockIdx.x * 256 + threadIdx.x;
    float s = 0.f, q = 0.f;
#pragma unroll
    for (int p = 0; p < 32; p++) { s += g_part_sum[p][c]; q += g_part_sq[p][c]; }
    const float m   = s * (1.f / B_);
    const float var = q * (1.f / B_) - m * m;
    const float sc  = gamma[c] / sqrtf(var + EPS_);
    g_scale[c] = sc;
    g_shift[c] = beta[c] - m * sc;
    if (blockIdx.x == 0 && threadIdx.x < E_) g_cnt[threadIdx.x] = 0;
}

__global__ void mlnn_bn_apply(float* __restrict__ h)
{
    const int idx = blockIdx.x * blockDim.x + threadIdx.x;   // float4 index
    float4* h4 = (float4*)h;
    const int c4 = idx & (H_ / 4 - 1);
    const float4 sc = ((const float4*)g_scale)[c4];
    const float4 sh = ((const float4*)g_shift)[c4];
    float4 v = h4[idx];
    v.x = v.x * sc.x + sh.x;
    v.y = v.y * sc.y + sh.y;
    v.z = v.z * sc.z + sh.z;
    v.w = v.w * sc.w + sh.w;
    h4[idx] = v;
}

// ---------------- routing: warp per row, argmax over E=8 logits --------------
__global__ __launch_bounds__(256)
void mlnn_routing(const float* __restrict__ h,
                  const float* __restrict__ W,    // [H,E]
                  const float* __restrict__ b)    // [E]
{
    __shared__ float Wt[E_ * H_];   // transposed: Wt[e*H + k], conflict-free reads
    const int tid = threadIdx.x;
    for (int i = tid; i < H_ * E_; i += 256) {
        const int k = i >> 3, e = i & 7;
        Wt[e * H_ + k] = W[i];
    }
    __syncthreads();
    const int warp = tid >> 5, lane = tid & 31;
    const int row  = blockIdx.x * 8 + warp;
    const float* hr = h + (size_t)row * H_;
    float acc[E_] = {};
#pragma unroll
    for (int i = 0; i < H_ / 32; i++) {
        const int k = i * 32 + lane;
        const float hv = hr[k];
#pragma unroll
        for (int e = 0; e < E_; e++) acc[e] += hv * Wt[e * H_ + k];
    }
#pragma unroll
    for (int e = 0; e < E_; e++)
#pragma unroll
        for (int off = 16; off; off >>= 1)
            acc[e] += __shfl_xor_sync(0xffffffffu, acc[e], off);
    if (lane == 0) {
        float best = acc[0] + b[0];
        int bi = 0;
#pragma unroll
        for (int e = 1; e < E_; e++) {
            const float v = acc[e] + b[e];
            if (v > best) { best = v; bi = e; }   // strict > == jnp first-max
        }
        g_act[row] = bi;
        atomicAdd(&g_cnt[bi], 1);
    }
}

__global__ void mlnn_scan()
{
    if (threadIdx.x == 0) {
        int s = 0;
#pragma unroll
        for (int e = 0; e < E_; e++) { g_off[e] = s; g_pos[e] = s; s += g_cnt[e]; }
    }
}

__global__ void mlnn_scatter()
{
    const int r = blockIdx.x * 256 + threadIdx.x;
    const int a = g_act[r];
    const int p = atomicAdd(&g_pos[a], 1);
    g_perm[p] = r;
}

// ---------------- launch ----------------
extern "C" void kernel_launch(void* const* d_in, const int* in_sizes, int n_in,
                              void* d_out, int out_size)
{
    const float* x     = (const float*)d_in[0];
    const float* dqn_W = (const float*)d_in[1];
    const float* dqn_b = (const float*)d_in[2];
    const float* Ws    = (const float*)d_in[3];
    const float* bs    = (const float*)d_in[4];
    const float* g0    = (const float*)d_in[5];
    const float* b0    = (const float*)d_in[6];
    const float* We    = (const float*)d_in[7];
    const float* be    = (const float*)d_in[8];
    const float* gmid  = (const float*)d_in[9];
    const float* bmid  = (const float*)d_in[10];
    const float* Wend  = (const float*)d_in[11];
    const float* bend  = (const float*)d_in[12];
    float* out = (float*)d_out;

    float *h, *y;
    cudaGetSymbolAddress((void**)&h, g_h);
    cudaGetSymbolAddress((void**)&y, g_y);

    // ---- start layer: h = relu(x @ Ws + bs); BN(g0,b0) ----
    mlnn_sgemm_bias_relu<<<dim3(H_ / 128, B_ / 128), 256>>>(x, Ws, bs, h, H_, DIN_);
    mlnn_bn_stats<<<dim3(H_ / 32, 32), dim3(32, 8)>>>(h);
    mlnn_bn_finalize<<<2, 256>>>(g0, b0);
    mlnn_bn_apply<<<(B_ * H_ / 4) / 256, 256>>>(h);

    float* cur = h;
    float* nxt = y;
    for (int l = 0; l < NMID_; l++) {
        mlnn_routing<<<B_ / 8, 256>>>(cur, dqn_W, dqn_b);
        mlnn_scan<<<1, 1>>>();
        mlnn_scatter<<<B_ / 256, 256>>>();
        mlnn_expert_sgemm<<<dim3(H_ / 128, B_ / 128, E_), 256>>>(
            cur, We + (size_t)l * E_ * H_ * H_, be + (size_t)l * E_ * H_, nxt);
        mlnn_bn_stats<<<dim3(H_ / 32, 32), dim3(32, 8)>>>(nxt);
        mlnn_bn_finalize<<<2, 256>>>(gmid + (size_t)l * H_, bmid + (size_t)l * H_);
        mlnn_bn_apply<<<(B_ * H_ / 4) / 256, 256>>>(nxt);
        float* t = cur; cur = nxt; nxt = t;
    }

    // ---- end layer: out = relu(h @ Wend + bend) ----
    mlnn_sgemm_bias_relu<<<dim3(DOUT_ / 128, B_ / 128), 256>>>(cur, Wend, bend, out, DOUT_, H_);
}

// round 6
// speedup vs baseline: 1.9159x; 1.9159x over previous
#include <cuda_runtime.h>
#include <cstdint>

#define B_    16384
#define DIN_  1024
#define H_    512
#define DOUT_ 256
#define E_    8
#define NMID_ 2
#define EPS_  1e-5f

// ---------------- scratch (device globals: no allocs allowed) ----------------
__device__ float g_h[B_ * H_];
__device__ float g_y[B_ * H_];
__device__ float g_part_sum[32][H_];
__device__ float g_part_sq[32][H_];
__device__ float g_scale[H_];
__device__ float g_shift[H_];
__device__ int   g_act[B_];
__device__ int   g_cnt[E_];
__device__ int   g_off[E_];
__device__ int   g_pos[E_];
__device__ int   g_perm[B_];

#define TRUNC10(v) (__uint_as_float(__float_as_uint(v) & 0xFFFFE000u))  // keep 10 mant bits (tf32)

__device__ __forceinline__ void mma_tf32(float* c, const uint32_t* a, const uint32_t* b) {
    asm volatile(
        "mma.sync.aligned.m16n8k8.row.col.f32.tf32.tf32.f32 "
        "{%0,%1,%2,%3}, {%4,%5,%6,%7}, {%8,%9}, {%0,%1,%2,%3};"
        : "+f"(c[0]), "+f"(c[1]), "+f"(c[2]), "+f"(c[3])
        : "r"(a[0]), "r"(a[1]), "r"(a[2]), "r"(a[3]), "r"(b[0]), "r"(b[1]));
}

// SMEM (floats): per buffer: Ah[128*36] Al[128*36] Bh[128*36] Bl[128*36]
#define PAD_     36
#define PARTF_   (128 * PAD_)          // 4608 floats per part
#define BUFF_    (4 * PARTF_)          // 18432 floats per buffer
#define SMEM_BYTES (2 * BUFF_ * 4)     // 147456 B

// ============ 3xTF32 mma.sync GEMM: C = relu(A @ W + bias) ============
// CTA tile 128x128, BK=32, 8 warps (2 m-groups x 4 n-groups), warp tile 64x32.
// A [*,KK] row-major (optional BN fuse + perm gather). W [KK,ldw] row-major.
template<int KK, bool EXPERT, bool BN>
__global__ __launch_bounds__(256, 1) void mma_gemm(
    const float* __restrict__ A,
    const float* __restrict__ W, int ldw,
    const float* __restrict__ biasAll,
    const float* __restrict__ bnS, const float* __restrict__ bnB,
    float* __restrict__ C, int ldc)
{
    constexpr int NC = KK / 32;
    extern __shared__ float smf[];

    const int tid  = threadIdx.x;
    const int wid  = tid >> 5;
    const int lane = tid & 31;
    const int gid  = lane >> 2;         // group id 0..7
    const int tig  = lane & 3;          // thread-in-group 0..3
    const int bm   = blockIdx.y * 128;
    const int bn0  = blockIdx.x * 128;

    int cnt = B_, pbase = 0;
    const float* Wp   = W;
    const float* bias = biasAll;
    if (EXPERT) {
        const int e = blockIdx.z;
        cnt = g_cnt[e];
        if (bm >= cnt) return;
        pbase = g_off[e];
        Wp    = W + (size_t)e * H_ * H_;
        bias  = biasAll + (size_t)e * H_;
    }

    // ---- fill assignments ----
    // A: thread -> (row = tid>>1, half = tid&1), 16 floats (4 x float4)
    const int arow = tid >> 1, ahalf = tid & 1;
    int grow = bm + arow;
    if (EXPERT) {
        const int lr = bm + arow;
        grow = g_perm[pbase + (lr < cnt ? lr : cnt - 1)];
    }
    const float* Arow = A + (size_t)grow * KK + ahalf * 16;
    // B: thread -> (kk = tid>>3 in 0..31, nl = tid&7), 16 scalars (n = nl+8j)
    const int bkk = tid >> 3, bnl = tid & 7;

    float4 a4[4];
    float  bb[16];

    auto loadRegs = [&](int c) {
        const int k0 = c * 32;
        const float4* Ap = (const float4*)(Arow + k0);
#pragma unroll
        for (int j = 0; j < 4; j++) a4[j] = Ap[j];
        if (BN) {
            const float4* s4 = (const float4*)(bnS + k0 + ahalf * 16);
            const float4* t4 = (const float4*)(bnB + k0 + ahalf * 16);
#pragma unroll
            for (int j = 0; j < 4; j++) {
                float4 s = s4[j], t = t4[j];
                a4[j].x = fmaf(a4[j].x, s.x, t.x);
                a4[j].y = fmaf(a4[j].y, s.y, t.y);
                a4[j].z = fmaf(a4[j].z, s.z, t.z);
                a4[j].w = fmaf(a4[j].w, s.w, t.w);
            }
        }
        const float* Wk = Wp + (size_t)(k0 + bkk) * ldw + bn0 + bnl;
#pragma unroll
        for (int j = 0; j < 16; j++) bb[j] = __ldg(Wk + 8 * j);
    };

    auto stash = [&](int buf) {
        float* Ah = smf + buf * BUFF_;
        float* Al = Ah + PARTF_;
        float* Bh = Al + PARTF_;
        float* Bl = Bh + PARTF_;
#pragma unroll
        for (int j = 0; j < 4; j++) {
            float4 hi, lo;
            hi.x = TRUNC10(a4[j].x); lo.x = a4[j].x - hi.x;
            hi.y = TRUNC10(a4[j].y); lo.y = a4[j].y - hi.y;
            hi.z = TRUNC10(a4[j].z); lo.z = a4[j].z - hi.z;
            hi.w = TRUNC10(a4[j].w); lo.w = a4[j].w - hi.w;
            const int o = arow * PAD_ + ahalf * 16 + j * 4;
            *(float4*)(Ah + o) = hi;
            *(float4*)(Al + o) = lo;
        }
#pragma unroll
        for (int j = 0; j < 16; j++) {
            const int n = bnl + 8 * j;
            const float hi = TRUNC10(bb[j]);
            Bh[n * PAD_ + bkk] = hi;
            Bl[n * PAD_ + bkk] = bb[j] - hi;
        }
    };

    // ---- accumulators ----
    float acc[4][4][4] = {};   // [mtile][ntile][frag]
    const int mbase = (wid & 1) * 64;
    const int nbase = (wid >> 1) * 32;

    auto domma = [&](int buf) {
        const uint32_t* Ah = (const uint32_t*)(smf + buf * BUFF_);
        const uint32_t* Al = Ah + PARTF_;
        const uint32_t* Bh = Al + PARTF_;
        const uint32_t* Bl = Bh + PARTF_;
#pragma unroll
        for (int ks = 0; ks < 4; ks++) {
            const int ko = ks * 8 + tig;
            uint32_t ah[4][4], al[4][4], bh[4][2], bl[4][2];
#pragma unroll
            for (int mt = 0; mt < 4; mt++) {
                const int r = (mbase + mt * 16 + gid) * PAD_ + ko;
                ah[mt][0] = Ah[r];              al[mt][0] = Al[r];
                ah[mt][1] = Ah[r + 8 * PAD_];   al[mt][1] = Al[r + 8 * PAD_];
                ah[mt][2] = Ah[r + 4];          al[mt][2] = Al[r + 4];
                ah[mt][3] = Ah[r + 8 * PAD_ + 4]; al[mt][3] = Al[r + 8 * PAD_ + 4];
            }
#pragma unroll
            for (int nt = 0; nt < 4; nt++) {
                const int r = (nbase + nt * 8 + gid) * PAD_ + ko;
                bh[nt][0] = Bh[r];      bl[nt][0] = Bl[r];
                bh[nt][1] = Bh[r + 4];  bl[nt][1] = Bl[r + 4];
            }
#pragma unroll
            for (int mt = 0; mt < 4; mt++)
#pragma unroll
                for (int nt = 0; nt < 4; nt++) {
                    mma_tf32(acc[mt][nt], ah[mt], bh[nt]);
                    mma_tf32(acc[mt][nt], ah[mt], bl[nt]);
                    mma_tf32(acc[mt][nt], al[mt], bh[nt]);
                }
        }
    };

    // ---- pipeline: prefetch regs -> stash -> sync -> (ldg next | mma | stash next) ----
    loadRegs(0);
    stash(0);
    __syncthreads();
    int buf = 0;
    for (int c = 0; c < NC; c++) {
        const bool more = (c + 1 < NC);
        if (more) loadRegs(c + 1);
        domma(buf);
        if (more) stash(buf ^ 1);
        __syncthreads();
        buf ^= 1;
    }

    // ---- epilogue: bias + relu, direct register stores ----
    // NOTE: lrow is the TILE-LOCAL row; the perm/guard index is bm + lrow
    // (round-3 bug: used lrow alone, dropping the bm block offset).
#pragma unroll
    for (int mt = 0; mt < 4; mt++) {
#pragma unroll
        for (int half = 0; half < 2; half++) {
            const int lrow = mbase + mt * 16 + gid + half * 8;   // 0..127
            bool valid = true;
            int orow = bm + lrow;
            if (EXPERT) {
                valid = (bm + lrow) < cnt;
                orow  = valid ? g_perm[pbase + bm + lrow] : 0;
            }
            if (!valid) continue;
            float* Cr = C + (size_t)orow * ldc + bn0;
#pragma unroll
            for (int nt = 0; nt < 4; nt++) {
                const int n = nbase + nt * 8 + tig * 2;
                const float2 bv = *(const float2*)(bias + bn0 + n);
                float2 o;
                o.x = fmaxf(acc[mt][nt][half * 2 + 0] + bv.x, 0.f);
                o.y = fmaxf(acc[mt][nt][half * 2 + 1] + bv.y, 0.f);
                *(float2*)(Cr + n) = o;
            }
        }
    }
}

// ---------------- BN stats: deterministic two-stage column reduction ---------
__global__ void mlnn_bn_stats(const float* __restrict__ h)
{
    __shared__ float ss[8][33];
    __shared__ float sq[8][33];
    const int col = blockIdx.x * 32 + threadIdx.x;
    const int r0  = blockIdx.y * 512;
    float s = 0.f, q = 0.f;
    for (int i = threadIdx.y; i < 512; i += 8) {
        float v = h[(size_t)(r0 + i) * H_ + col];
        s += v; q += v * v;
    }
    ss[threadIdx.y][threadIdx.x] = s;
    sq[threadIdx.y][threadIdx.x] = q;
    __syncthreads();
    if (threadIdx.y == 0) {
#pragma unroll
        for (int y = 1; y < 8; y++) { s += ss[y][threadIdx.x]; q += sq[y][threadIdx.x]; }
        g_part_sum[blockIdx.y][col] = s;
        g_part_sq[blockIdx.y][col]  = q;
    }
}

__global__ void mlnn_bn_finalize(const float* __restrict__ gamma,
                                 const float* __restrict__ beta)
{
    const int c = blockIdx.x * 256 + threadIdx.x;
    float s = 0.f, q = 0.f;
#pragma unroll
    for (int p = 0; p < 32; p++) { s += g_part_sum[p][c]; q += g_part_sq[p][c]; }
    const float m   = s * (1.f / B_);
    const float var = q * (1.f / B_) - m * m;
    const float sc  = gamma[c] / sqrtf(var + EPS_);
    g_scale[c] = sc;
    g_shift[c] = beta[c] - m * sc;
    if (blockIdx.x == 0 && threadIdx.x < E_) g_cnt[threadIdx.x] = 0;
}

// ---------------- routing: warp per row, BN fused into load ----------------
__global__ __launch_bounds__(256)
void mlnn_routing(const float* __restrict__ h,
                  const float* __restrict__ W,    // [H,E]
                  const float* __restrict__ b)    // [E]
{
    __shared__ float Wt[E_ * H_];
    const int tid = threadIdx.x;
    for (int i = tid; i < H_ * E_; i += 256) {
        const int k = i >> 3, e = i & 7;
        Wt[e * H_ + k] = W[i];
    }
    __syncthreads();
    const int warp = tid >> 5, lane = tid & 31;
    const int row  = blockIdx.x * 8 + warp;
    const float* hr = h + (size_t)row * H_;
    float acc[E_] = {};
#pragma unroll
    for (int i = 0; i < H_ / 32; i++) {
        const int k = i * 32 + lane;
        const float hv = fmaf(hr[k], g_scale[k], g_shift[k]);
#pragma unroll
        for (int e = 0; e < E_; e++) acc[e] += hv * Wt[e * H_ + k];
    }
#pragma unroll
    for (int e = 0; e < E_; e++)
#pragma unroll
        for (int off = 16; off; off >>= 1)
            acc[e] += __shfl_xor_sync(0xffffffffu, acc[e], off);
    if (lane == 0) {
        float best = acc[0] + b[0];
        int bi = 0;
#pragma unroll
        for (int e = 1; e < E_; e++) {
            const float v = acc[e] + b[e];
            if (v > best) { best = v; bi = e; }
        }
        g_act[row] = bi;
        atomicAdd(&g_cnt[bi], 1);
    }
}

__global__ void mlnn_scan()
{
    if (threadIdx.x == 0) {
        int s = 0;
#pragma unroll
        for (int e = 0; e < E_; e++) { g_off[e] = s; g_pos[e] = s; s += g_cnt[e]; }
    }
}

__global__ void mlnn_scatter()
{
    const int r = blockIdx.x * 256 + threadIdx.x;
    const int a = g_act[r];
    const int p = atomicAdd(&g_pos[a], 1);
    g_perm[p] = r;
}

// ---------------- launch ----------------
extern "C" void kernel_launch(void* const* d_in, const int* in_sizes, int n_in,
                              void* d_out, int out_size)
{
    const float* x     = (const float*)d_in[0];
    const float* dqn_W = (const float*)d_in[1];
    const float* dqn_b = (const float*)d_in[2];
    const float* Ws    = (const float*)d_in[3];
    const float* bs    = (const float*)d_in[4];
    const float* g0    = (const float*)d_in[5];
    const float* b0    = (const float*)d_in[6];
    const float* We    = (const float*)d_in[7];
    const float* be    = (const float*)d_in[8];
    const float* gmid  = (const float*)d_in[9];
    const float* bmid  = (const float*)d_in[10];
    const float* Wend  = (const float*)d_in[11];
    const float* bend  = (const float*)d_in[12];
    float* out = (float*)d_out;

    float *h, *y, *scl, *shf;
    cudaGetSymbolAddress((void**)&h,   g_h);
    cudaGetSymbolAddress((void**)&y,   g_y);
    cudaGetSymbolAddress((void**)&scl, g_scale);
    cudaGetSymbolAddress((void**)&shf, g_shift);

    cudaFuncSetAttribute(mma_gemm<1024, false, false>,
                         cudaFuncAttributeMaxDynamicSharedMemorySize, SMEM_BYTES);
    cudaFuncSetAttribute(mma_gemm<512, true, true>,
                         cudaFuncAttributeMaxDynamicSharedMemorySize, SMEM_BYTES);
    cudaFuncSetAttribute(mma_gemm<512, false, true>,
                         cudaFuncAttributeMaxDynamicSharedMemorySize, SMEM_BYTES);

    // ---- start layer: h = relu(x @ Ws + bs); BN stats/finalize ----
    mma_gemm<1024, false, false><<<dim3(H_ / 128, B_ / 128), 256, SMEM_BYTES>>>(
        x, Ws, H_, bs, nullptr, nullptr, h, H_);
    mlnn_bn_stats<<<dim3(H_ / 32, 32), dim3(32, 8)>>>(h);
    mlnn_bn_finalize<<<2, 256>>>(g0, b0);

    float* cur = h;
    float* nxt = y;
    for (int l = 0; l < NMID_; l++) {
        mlnn_routing<<<B_ / 8, 256>>>(cur, dqn_W, dqn_b);
        mlnn_scan<<<1, 1>>>();
        mlnn_scatter<<<B_ / 256, 256>>>();
        mma_gemm<512, true, true><<<dim3(H_ / 128, B_ / 128, E_), 256, SMEM_BYTES>>>(
            cur, We + (size_t)l * E_ * H_ * H_, H_,
            be + (size_t)l * E_ * H_, scl, shf, nxt, H_);
        mlnn_bn_stats<<<dim3(H_ / 32, 32), dim3(32, 8)>>>(nxt);
        mlnn_bn_finalize<<<2, 256>>>(gmid + (size_t)l * H_, bmid + (size_t)l * H_);
        float* t = cur; cur = nxt; nxt = t;
    }

    // ---- end layer: out = relu(h @ Wend + bend), BN of last layer fused ----
    mma_gemm<512, false, true><<<dim3(DOUT_ / 128, B_ / 128), 256, SMEM_BYTES>>>(
        cur, Wend, DOUT_, bend, scl, shf, out, DOUT_);
}

// round 9
// speedup vs baseline: 1.9918x; 1.0396x over previous
#include <cuda_runtime.h>
#include <cstdint>

#define B_    16384
#define DIN_  1024
#define H_    512
#define DOUT_ 256
#define E_    8
#define NMID_ 2
#define EPS_  1e-5f

// ---------------- scratch (device globals: no allocs allowed) ----------------
__device__ float g_h[B_ * H_];
__device__ float g_y[B_ * H_];
__device__ float g_part_sum[32][H_];
__device__ float g_part_sq[32][H_];
__device__ float g_scale[H_];
__device__ float g_shift[H_];
__device__ int   g_act[B_];
__device__ int   g_cnt[E_];
__device__ int   g_off[E_];
__device__ int   g_pos[E_];
__device__ int   g_perm[B_];

#define TRUNC10(v) (__uint_as_float(__float_as_uint(v) & 0xFFFFE000u))  // keep 10 mant bits (tf32)

__device__ __forceinline__ void mma_tf32(float* c, const uint32_t* a, const uint32_t* b) {
    asm volatile(
        "mma.sync.aligned.m16n8k8.row.col.f32.tf32.tf32.f32 "
        "{%0,%1,%2,%3}, {%4,%5,%6,%7}, {%8,%9}, {%0,%1,%2,%3};"
        : "+f"(c[0]), "+f"(c[1]), "+f"(c[2]), "+f"(c[3])
        : "r"(a[0]), "r"(a[1]), "r"(a[2]), "r"(a[3]), "r"(b[0]), "r"(b[1]));
}
// one x4 = four 8-row x 16B matrices; lane l of each matrix gets word (l&3) of row (l>>2)
__device__ __forceinline__ void ldsm4(uint32_t* r, uint32_t saddr) {
    asm volatile("ldmatrix.sync.aligned.m8n8.x4.shared.b16 {%0,%1,%2,%3}, [%4];"
                 : "=r"(r[0]), "=r"(r[1]), "=r"(r[2]), "=r"(r[3]) : "r"(saddr));
}

// SMEM (floats): per buffer: Ah[128*36] Al[128*36] Bh[128*36] Bl[128*36]
#define PAD_     36
#define PARTF_   (128 * PAD_)          // 4608 floats per part
#define BUFF_    (4 * PARTF_)          // 18432 floats per buffer
#define PART_B   (PARTF_ * 4)         // bytes
#define BUFF_B   (BUFF_ * 4)          // bytes
#define SMEM_BYTES (2 * BUFF_B)       // 147456 B

// ============ 3xTF32 mma.sync GEMM: C = relu(A @ W + bias) ============
// CTA tile 128x128, BK=32, 8 warps (2 m-groups x 4 n-groups), warp tile 64x32.
// A [*,KK] row-major (optional BN fuse + perm gather). W [KK,ldw] row-major.
template<int KK, bool EXPERT, bool BN>
__global__ __launch_bounds__(256, 1) void mma_gemm(
    const float* __restrict__ A,
    const float* __restrict__ W, int ldw,
    const float* __restrict__ biasAll,
    const float* __restrict__ bnS, const float* __restrict__ bnB,
    float* __restrict__ C, int ldc)
{
    constexpr int NC = KK / 32;
    extern __shared__ float smf[];

    const int tid  = threadIdx.x;
    const int wid  = tid >> 5;
    const int lane = tid & 31;
    const int gid  = lane >> 2;         // group id 0..7
    const int tig  = lane & 3;          // thread-in-group 0..3
    const int bm   = blockIdx.y * 128;
    const int bn0  = blockIdx.x * 128;

    int cnt = B_, pbase = 0;
    const float* Wp   = W;
    const float* bias = biasAll;
    if (EXPERT) {
        const int e = blockIdx.z;
        cnt = g_cnt[e];
        if (bm >= cnt) return;
        pbase = g_off[e];
        Wp    = W + (size_t)e * H_ * H_;
        bias  = biasAll + (size_t)e * H_;
    }

    // ---- fill assignments ----
    // A: thread -> (row = tid>>1, half = tid&1), 16 floats (4 x float4)
    const int arow = tid >> 1, ahalf = tid & 1;
    int grow = bm + arow;
    if (EXPERT) {
        const int lr = bm + arow;
        grow = g_perm[pbase + (lr < cnt ? lr : cnt - 1)];
    }
    const float* Arow = A + (size_t)grow * KK + ahalf * 16;
    // B: thread -> (kk = tid>>3 in 0..31, nl = tid&7), 16 scalars (n = nl+8j)
    const int bkk = tid >> 3, bnl = tid & 7;

    float4 a4[4];
    float  bb[16];

    auto loadRegs = [&](int c) {
        const int k0 = c * 32;
        const float4* Ap = (const float4*)(Arow + k0);
#pragma unroll
        for (int j = 0; j < 4; j++) a4[j] = Ap[j];
        if (BN) {
            const float4* s4 = (const float4*)(bnS + k0 + ahalf * 16);
            const float4* t4 = (const float4*)(bnB + k0 + ahalf * 16);
#pragma unroll
            for (int j = 0; j < 4; j++) {
                float4 s = s4[j], t = t4[j];
                a4[j].x = fmaf(a4[j].x, s.x, t.x);
                a4[j].y = fmaf(a4[j].y, s.y, t.y);
                a4[j].z = fmaf(a4[j].z, s.z, t.z);
                a4[j].w = fmaf(a4[j].w, s.w, t.w);
            }
        }
        const float* Wk = Wp + (size_t)(k0 + bkk) * ldw + bn0 + bnl;
#pragma unroll
        for (int j = 0; j < 16; j++) bb[j] = __ldg(Wk + 8 * j);
    };

    auto stash = [&](int buf) {
        float* Ah = smf + buf * BUFF_;
        float* Al = Ah + PARTF_;
        float* Bh = Al + PARTF_;
        float* Bl = Bh + PARTF_;
#pragma unroll
        for (int j = 0; j < 4; j++) {
            float4 hi, lo;
            hi.x = TRUNC10(a4[j].x); lo.x = a4[j].x - hi.x;
            hi.y = TRUNC10(a4[j].y); lo.y = a4[j].y - hi.y;
            hi.z = TRUNC10(a4[j].z); lo.z = a4[j].z - hi.z;
            hi.w = TRUNC10(a4[j].w); lo.w = a4[j].w - hi.w;
            const int o = arow * PAD_ + ahalf * 16 + j * 4;
            *(float4*)(Ah + o) = hi;
            *(float4*)(Al + o) = lo;
        }
#pragma unroll
        for (int j = 0; j < 16; j++) {
            const int n = bnl + 8 * j;
            const float hi = TRUNC10(bb[j]);
            Bh[n * PAD_ + bkk] = hi;
            Bl[n * PAD_ + bkk] = bb[j] - hi;
        }
    };

    // ---- accumulators ----
    float acc[4][4][4] = {};   // [mtile][ntile][frag]
    const int mbase = (wid & 1) * 64;
    const int nbase = (wid >> 1) * 32;

    // ldmatrix lane-address offsets (bytes, within a part)
    // A x4: m0/m1 = rows (mbase+mt*16)+0..15 at col-word 0; m2/m3 same rows col-word +4
    const uint32_t sbase = (uint32_t)__cvta_generic_to_shared(smf);
    const uint32_t aLane = (uint32_t)(((mbase + (lane & 15)) * PAD_ + (lane >> 4) * 4) * 4);
    // B x4: rows (nbase+nt*8)+0..7; matrices at k-words kp*16 + {0,4,8,12}
    const uint32_t bLane = (uint32_t)(((nbase + (lane & 7)) * PAD_ + (lane >> 3) * 4) * 4);

    auto domma = [&](int buf) {
        const uint32_t aH = sbase + buf * BUFF_B + aLane;
        const uint32_t aL = aH + PART_B;
        const uint32_t bH = sbase + buf * BUFF_B + 2 * PART_B + bLane;
        const uint32_t bL = bH + PART_B;
#pragma unroll
        for (int kp = 0; kp < 2; kp++) {               // two k-step pairs per chunk
            uint32_t bh[4][4], bl[4][4];               // [nt][{b0,b1}ks0, {b0,b1}ks1]
#pragma unroll
            for (int nt = 0; nt < 4; nt++) {
                const uint32_t off = (uint32_t)((nt * 8 * PAD_ + kp * 16) * 4);
                ldsm4(bh[nt], bH + off);
                ldsm4(bl[nt], bL + off);
            }
#pragma unroll
            for (int sub = 0; sub < 2; sub++) {
                const int ks = kp * 2 + sub;
#pragma unroll
                for (int mt = 0; mt < 4; mt++) {
                    uint32_t ah[4], al[4];
                    const uint32_t off = (uint32_t)((mt * 16 * PAD_ + ks * 8) * 4);
                    ldsm4(ah, aH + off);
                    ldsm4(al, aL + off);
#pragma unroll
                    for (int nt = 0; nt < 4; nt++) {
                        mma_tf32(acc[mt][nt], ah, &bh[nt][sub * 2]);
                        mma_tf32(acc[mt][nt], ah, &bl[nt][sub * 2]);
                        mma_tf32(acc[mt][nt], al, &bh[nt][sub * 2]);
                    }
                }
            }
        }
    };

    // ---- pipeline: prefetch regs -> stash -> sync -> (ldg next | mma | stash next) ----
    loadRegs(0);
    stash(0);
    __syncthreads();
    int buf = 0;
    for (int c = 0; c < NC; c++) {
        const bool more = (c + 1 < NC);
        if (more) loadRegs(c + 1);
        domma(buf);
        if (more) stash(buf ^ 1);
        __syncthreads();
        buf ^= 1;
    }

    // ---- epilogue: bias + relu, direct register stores ----
#pragma unroll
    for (int mt = 0; mt < 4; mt++) {
#pragma unroll
        for (int half = 0; half < 2; half++) {
            const int lrow = mbase + mt * 16 + gid + half * 8;   // tile-local 0..127
            bool valid = true;
            int orow = bm + lrow;
            if (EXPERT) {
                valid = (bm + lrow) < cnt;
                orow  = valid ? g_perm[pbase + bm + lrow] : 0;
            }
            if (!valid) continue;
            float* Cr = C + (size_t)orow * ldc + bn0;
#pragma unroll
            for (int nt = 0; nt < 4; nt++) {
                const int n = nbase + nt * 8 + tig * 2;
                const float2 bv = *(const float2*)(bias + bn0 + n);
                float2 o;
                o.x = fmaxf(acc[mt][nt][half * 2 + 0] + bv.x, 0.f);
                o.y = fmaxf(acc[mt][nt][half * 2 + 1] + bv.y, 0.f);
                *(float2*)(Cr + n) = o;
            }
        }
    }
}

// ---------------- BN stats: deterministic two-stage column reduction ---------
__global__ void mlnn_bn_stats(const float* __restrict__ h)
{
    __shared__ float ss[8][33];
    __shared__ float sq[8][33];
    const int col = blockIdx.x * 32 + threadIdx.x;
    const int r0  = blockIdx.y * 512;
    float s = 0.f, q = 0.f;
    for (int i = threadIdx.y; i < 512; i += 8) {
        float v = h[(size_t)(r0 + i) * H_ + col];
        s += v; q += v * v;
    }
    ss[threadIdx.y][threadIdx.x] = s;
    sq[threadIdx.y][threadIdx.x] = q;
    __syncthreads();
    if (threadIdx.y == 0) {
#pragma unroll
        for (int y = 1; y < 8; y++) { s += ss[y][threadIdx.x]; q += sq[y][threadIdx.x]; }
        g_part_sum[blockIdx.y][col] = s;
        g_part_sq[blockIdx.y][col]  = q;
    }
}

__global__ void mlnn_bn_finalize(const float* __restrict__ gamma,
                                 const float* __restrict__ beta)
{
    const int c = blockIdx.x * 256 + threadIdx.x;
    float s = 0.f, q = 0.f;
#pragma unroll
    for (int p = 0; p < 32; p++) { s += g_part_sum[p][c]; q += g_part_sq[p][c]; }
    const float m   = s * (1.f / B_);
    const float var = q * (1.f / B_) - m * m;
    const float sc  = gamma[c] / sqrtf(var + EPS_);
    g_scale[c] = sc;
    g_shift[c] = beta[c] - m * sc;
    if (blockIdx.x == 0 && threadIdx.x < E_) g_cnt[threadIdx.x] = 0;
}

// ---------------- routing: warp per row, BN fused into load ----------------
__global__ __launch_bounds__(256)
void mlnn_routing(const float* __restrict__ h,
                  const float* __restrict__ W,    // [H,E]
                  const float* __restrict__ b)    // [E]
{
    __shared__ float Wt[E_ * H_];
    const int tid = threadIdx.x;
    for (int i = tid; i < H_ * E_; i += 256) {
        const int k = i >> 3, e = i & 7;
        Wt[e * H_ + k] = W[i];
    }
    __syncthreads();
    const int warp = tid >> 5, lane = tid & 31;
    const int row  = blockIdx.x * 8 + warp;
    const float* hr = h + (size_t)row * H_;
    float acc[E_] = {};
#pragma unroll
    for (int i = 0; i < H_ / 32; i++) {
        const int k = i * 32 + lane;
        const float hv = fmaf(hr[k], g_scale[k], g_shift[k]);
#pragma unroll
        for (int e = 0; e < E_; e++) acc[e] += hv * Wt[e * H_ + k];
    }
#pragma unroll
    for (int e = 0; e < E_; e++)
#pragma unroll
        for (int off = 16; off; off >>= 1)
            acc[e] += __shfl_xor_sync(0xffffffffu, acc[e], off);
    if (lane == 0) {
        float best = acc[0] + b[0];
        int bi = 0;
#pragma unroll
        for (int e = 1; e < E_; e++) {
            const float v = acc[e] + b[e];
            if (v > best) { best = v; bi = e; }
        }
        g_act[row] = bi;
        atomicAdd(&g_cnt[bi], 1);
    }
}

__global__ void mlnn_scan()
{
    if (threadIdx.x == 0) {
        int s = 0;
#pragma unroll
        for (int e = 0; e < E_; e++) { g_off[e] = s; g_pos[e] = s; s += g_cnt[e]; }
    }
}

__global__ void mlnn_scatter()
{
    const int r = blockIdx.x * 256 + threadIdx.x;
    const int a = g_act[r];
    const int p = atomicAdd(&g_pos[a], 1);
    g_perm[p] = r;
}

// ---------------- launch ----------------
extern "C" void kernel_launch(void* const* d_in, const int* in_sizes, int n_in,
                              void* d_out, int out_size)
{
    const float* x     = (const float*)d_in[0];
    const float* dqn_W = (const float*)d_in[1];
    const float* dqn_b = (const float*)d_in[2];
    const float* Ws    = (const float*)d_in[3];
    const float* bs    = (const float*)d_in[4];
    const float* g0    = (const float*)d_in[5];
    const float* b0    = (const float*)d_in[6];
    const float* We    = (const float*)d_in[7];
    const float* be    = (const float*)d_in[8];
    const float* gmid  = (const float*)d_in[9];
    const float* bmid  = (const float*)d_in[10];
    const float* Wend  = (const float*)d_in[11];
    const float* bend  = (const float*)d_in[12];
    float* out = (float*)d_out;

    float *h, *y, *scl, *shf;
    cudaGetSymbolAddress((void**)&h,   g_h);
    cudaGetSymbolAddress((void**)&y,   g_y);
    cudaGetSymbolAddress((void**)&scl, g_scale);
    cudaGetSymbolAddress((void**)&shf, g_shift);

    cudaFuncSetAttribute(mma_gemm<1024, false, false>,
                         cudaFuncAttributeMaxDynamicSharedMemorySize, SMEM_BYTES);
    cudaFuncSetAttribute(mma_gemm<512, true, true>,
                         cudaFuncAttributeMaxDynamicSharedMemorySize, SMEM_BYTES);
    cudaFuncSetAttribute(mma_gemm<512, false, true>,
                         cudaFuncAttributeMaxDynamicSharedMemorySize, SMEM_BYTES);

    // ---- start layer: h = relu(x @ Ws + bs); BN stats/finalize ----
    mma_gemm<1024, false, false><<<dim3(H_ / 128, B_ / 128), 256, SMEM_BYTES>>>(
        x, Ws, H_, bs, nullptr, nullptr, h, H_);
    mlnn_bn_stats<<<dim3(H_ / 32, 32), dim3(32, 8)>>>(h);
    mlnn_bn_finalize<<<2, 256>>>(g0, b0);

    float* cur = h;
    float* nxt = y;
    for (int l = 0; l < NMID_; l++) {
        mlnn_routing<<<B_ / 8, 256>>>(cur, dqn_W, dqn_b);
        mlnn_scan<<<1, 1>>>();
        mlnn_scatter<<<B_ / 256, 256>>>();
        mma_gemm<512, true, true><<<dim3(H_ / 128, B_ / 128, E_), 256, SMEM_BYTES>>>(
            cur, We + (size_t)l * E_ * H_ * H_, H_,
            be + (size_t)l * E_ * H_, scl, shf, nxt, H_);
        mlnn_bn_stats<<<dim3(H_ / 32, 32), dim3(32, 8)>>>(nxt);
        mlnn_bn_finalize<<<2, 256>>>(gmid + (size_t)l * H_, bmid + (size_t)l * H_);
        float* t = cur; cur = nxt; nxt = t;
    }

    // ---- end layer: out = relu(h @ Wend + bend), BN of last layer fused ----
    mma_gemm<512, false, true><<<dim3(DOUT_ / 128, B_ / 128), 256, SMEM_BYTES>>>(
        cur, Wend, DOUT_, bend, scl, shf, out, DOUT_);
}

// round 10
// speedup vs baseline: 2.8328x; 1.4223x over previous
#include <cuda_runtime.h>
#include <cuda_fp16.h>
#include <cstdint>

#define B_    16384
#define DIN_  1024
#define H_    512
#define DOUT_ 256
#define E_    8
#define NMID_ 2
#define EPS_  1e-5f

// ---------------- scratch (device globals: no allocs allowed) ----------------
__device__ float g_h[B_ * H_];
__device__ float g_y[B_ * H_];
__device__ float g_part_sum[32][H_];
__device__ float g_part_sq[32][H_];
__device__ float g_scale[H_];
__device__ float g_shift[H_];
__device__ int   g_act[B_];
__device__ int   g_cnt[E_];
__device__ int   g_off[E_];
__device__ int   g_pos[E_];
__device__ int   g_perm[B_];

__device__ __forceinline__ void mma_f16(float* c, const uint32_t* a, const uint32_t* b) {
    asm volatile(
        "mma.sync.aligned.m16n8k16.row.col.f32.f16.f16.f32 "
        "{%0,%1,%2,%3}, {%4,%5,%6,%7}, {%8,%9}, {%0,%1,%2,%3};"
        : "+f"(c[0]), "+f"(c[1]), "+f"(c[2]), "+f"(c[3])
        : "r"(a[0]), "r"(a[1]), "r"(a[2]), "r"(a[3]), "r"(b[0]), "r"(b[1]));
}
__device__ __forceinline__ void ldsm4(uint32_t* r, uint32_t saddr) {
    asm volatile("ldmatrix.sync.aligned.m8n8.x4.shared.b16 {%0,%1,%2,%3}, [%4];"
                 : "=r"(r[0]), "=r"(r[1]), "=r"(r[2]), "=r"(r[3]) : "r"(saddr));
}

// SMEM (fp16): per buffer: Ah[128*40] Al[128*40] Bh[128*40] Bl[128*40]
#define PADH_    40                     // fp16 units per row (80 B stride)
#define ROWB_    (PADH_ * 2)            // 80 bytes
#define PART_B   (128 * ROWB_)          // 10240 B per part
#define BUFF_B   (4 * PART_B)           // 40960 B per buffer
#define SMEM_BYTES (2 * BUFF_B)         // 81920 B

// ============ 3xFP16-split mma.sync GEMM: C = relu(A @ W + bias) ============
// CTA tile 128x128, BK=32, 8 warps (2 m-groups x 4 n-groups), warp tile 64x32.
// A [*,KK] row-major (optional BN fuse + perm gather). W [KK,ldw] row-major.
template<int KK, bool EXPERT, bool BN>
__global__ __launch_bounds__(256, 2) void mma_gemm(
    const float* __restrict__ A,
    const float* __restrict__ W, int ldw,
    const float* __restrict__ biasAll,
    const float* __restrict__ bnS, const float* __restrict__ bnB,
    float* __restrict__ C, int ldc)
{
    constexpr int NC = KK / 32;
    extern __shared__ __half smh[];

    const int tid  = threadIdx.x;
    const int wid  = tid >> 5;
    const int lane = tid & 31;
    const int gid  = lane >> 2;
    const int tig  = lane & 3;
    const int bm   = blockIdx.y * 128;
    const int bn0  = blockIdx.x * 128;

    int cnt = B_, pbase = 0;
    const float* Wp   = W;
    const float* bias = biasAll;
    if (EXPERT) {
        const int e = blockIdx.z;
        cnt = g_cnt[e];
        if (bm >= cnt) return;
        pbase = g_off[e];
        Wp    = W + (size_t)e * H_ * H_;
        bias  = biasAll + (size_t)e * H_;
    }

    // ---- fill assignments ----
    const int arow = tid >> 1, ahalf = tid & 1;
    int grow = bm + arow;
    if (EXPERT) {
        const int lr = bm + arow;
        grow = g_perm[pbase + (lr < cnt ? lr : cnt - 1)];
    }
    const float* Arow = A + (size_t)grow * KK + ahalf * 16;
    const int bkk = tid >> 3, bnl = tid & 7;

    float4 a4[4];
    float  bb[16];

    auto loadRegs = [&](int c) {
        const int k0 = c * 32;
        const float4* Ap = (const float4*)(Arow + k0);
#pragma unroll
        for (int j = 0; j < 4; j++) a4[j] = Ap[j];
        if (BN) {
            const float4* s4 = (const float4*)(bnS + k0 + ahalf * 16);
            const float4* t4 = (const float4*)(bnB + k0 + ahalf * 16);
#pragma unroll
            for (int j = 0; j < 4; j++) {
                float4 s = s4[j], t = t4[j];
                a4[j].x = fmaf(a4[j].x, s.x, t.x);
                a4[j].y = fmaf(a4[j].y, s.y, t.y);
                a4[j].z = fmaf(a4[j].z, s.z, t.z);
                a4[j].w = fmaf(a4[j].w, s.w, t.w);
            }
        }
        const float* Wk = Wp + (size_t)(k0 + bkk) * ldw + bn0 + bnl;
#pragma unroll
        for (int j = 0; j < 16; j++) bb[j] = __ldg(Wk + 8 * j);
    };

    auto stash = [&](int buf) {
        __half* Ah = smh + buf * (BUFF_B / 2);
        __half* Al = Ah + PART_B / 2;
        __half* Bh = Al + PART_B / 2;
        __half* Bl = Bh + PART_B / 2;
#pragma unroll
        for (int j = 0; j < 4; j++) {
            const float v[4] = { a4[j].x, a4[j].y, a4[j].z, a4[j].w };
            __half hi[4], lo[4];
#pragma unroll
            for (int q = 0; q < 4; q++) {
                hi[q] = __float2half_rn(v[q]);
                lo[q] = __float2half_rn(v[q] - __half2float(hi[q]));
            }
            const int o = arow * PADH_ + ahalf * 16 + j * 4;   // fp16 units, 8B aligned
            *(__half2*)(Ah + o)     = __halves2half2(hi[0], hi[1]);
            *(__half2*)(Ah + o + 2) = __halves2half2(hi[2], hi[3]);
            *(__half2*)(Al + o)     = __halves2half2(lo[0], lo[1]);
            *(__half2*)(Al + o + 2) = __halves2half2(lo[2], lo[3]);
        }
#pragma unroll
        for (int j = 0; j < 16; j++) {
            const int n = bnl + 8 * j;
            const __half hi = __float2half_rn(bb[j]);
            Bh[n * PADH_ + bkk] = hi;
            Bl[n * PADH_ + bkk] = __float2half_rn(bb[j] - __half2float(hi));
        }
    };

    // ---- accumulators ----
    float acc[4][4][4] = {};   // [mtile][ntile][frag]
    const int mbase = (wid & 1) * 64;
    const int nbase = (wid >> 1) * 32;

    const uint32_t sbase = (uint32_t)__cvta_generic_to_shared(smh);
    // A x4 (per mt,ks16): m0/m1 rows 0..15 k0-7, m2/m3 rows 0..15 k8-15
    const uint32_t aLane = (uint32_t)((mbase + (lane & 15)) * ROWB_ + (lane >> 4) * 16);
    // B x4 (per ntpair,ks16): mi=lane>>3: {nt0 k0-7, nt0 k8-15, nt1 k0-7, nt1 k8-15}
    const uint32_t bLane = (uint32_t)((nbase + (((lane >> 3) >> 1) * 8) + (lane & 7)) * ROWB_
                                      + ((lane >> 3) & 1) * 16);

    auto domma = [&](int buf) {
        const uint32_t aH = sbase + buf * BUFF_B + aLane;
        const uint32_t aL = aH + PART_B;
        const uint32_t bH = sbase + buf * BUFF_B + 2 * PART_B + bLane;
        const uint32_t bL = bH + PART_B;
#pragma unroll
        for (int ks = 0; ks < 2; ks++) {               // two k16 steps per chunk
            uint32_t bh[2][4], bl[2][4];               // [ntp][nt_even b0,b1, nt_odd b0,b1]
#pragma unroll
            for (int ntp = 0; ntp < 2; ntp++) {
                const uint32_t off = (uint32_t)(ntp * 16 * ROWB_ + ks * 32);
                ldsm4(bh[ntp], bH + off);
                ldsm4(bl[ntp], bL + off);
            }
#pragma unroll
            for (int mt = 0; mt < 4; mt++) {
                uint32_t ah[4], al[4];
                const uint32_t off = (uint32_t)(mt * 16 * ROWB_ + ks * 32);
                ldsm4(ah, aH + off);
                ldsm4(al, aL + off);
#pragma unroll
                for (int nt = 0; nt < 4; nt++) {
                    const uint32_t* bhp = &bh[nt >> 1][(nt & 1) * 2];
                    const uint32_t* blp = &bl[nt >> 1][(nt & 1) * 2];
                    mma_f16(acc[mt][nt], ah, bhp);
                    mma_f16(acc[mt][nt], ah, blp);
                    mma_f16(acc[mt][nt], al, bhp);
                }
            }
        }
    };

    // ---- pipeline ----
    loadRegs(0);
    stash(0);
    __syncthreads();
    int buf = 0;
    for (int c = 0; c < NC; c++) {
        const bool more = (c + 1 < NC);
        if (more) loadRegs(c + 1);
        domma(buf);
        if (more) stash(buf ^ 1);
        __syncthreads();
        buf ^= 1;
    }

    // ---- epilogue: bias + relu, direct register stores ----
#pragma unroll
    for (int mt = 0; mt < 4; mt++) {
#pragma unroll
        for (int half = 0; half < 2; half++) {
            const int lrow = mbase + mt * 16 + gid + half * 8;   // tile-local 0..127
            bool valid = true;
            int orow = bm + lrow;
            if (EXPERT) {
                valid = (bm + lrow) < cnt;
                orow  = valid ? g_perm[pbase + bm + lrow] : 0;
            }
            if (!valid) continue;
            float* Cr = C + (size_t)orow * ldc + bn0;
#pragma unroll
            for (int nt = 0; nt < 4; nt++) {
                const int n = nbase + nt * 8 + tig * 2;
                const float2 bv = *(const float2*)(bias + bn0 + n);
                float2 o;
                o.x = fmaxf(acc[mt][nt][half * 2 + 0] + bv.x, 0.f);
                o.y = fmaxf(acc[mt][nt][half * 2 + 1] + bv.y, 0.f);
                *(float2*)(Cr + n) = o;
            }
        }
    }
}

// ---------------- BN stats: deterministic two-stage column reduction ---------
__global__ void mlnn_bn_stats(const float* __restrict__ h)
{
    __shared__ float ss[8][33];
    __shared__ float sq[8][33];
    const int col = blockIdx.x * 32 + threadIdx.x;
    const int r0  = blockIdx.y * 512;
    float s = 0.f, q = 0.f;
    for (int i = threadIdx.y; i < 512; i += 8) {
        float v = h[(size_t)(r0 + i) * H_ + col];
        s += v; q += v * v;
    }
    ss[threadIdx.y][threadIdx.x] = s;
    sq[threadIdx.y][threadIdx.x] = q;
    __syncthreads();
    if (threadIdx.y == 0) {
#pragma unroll
        for (int y = 1; y < 8; y++) { s += ss[y][threadIdx.x]; q += sq[y][threadIdx.x]; }
        g_part_sum[blockIdx.y][col] = s;
        g_part_sq[blockIdx.y][col]  = q;
    }
}

__global__ void mlnn_bn_finalize(const float* __restrict__ gamma,
                                 const float* __restrict__ beta)
{
    const int c = blockIdx.x * 256 + threadIdx.x;
    float s = 0.f, q = 0.f;
#pragma unroll
    for (int p = 0; p < 32; p++) { s += g_part_sum[p][c]; q += g_part_sq[p][c]; }
    const float m   = s * (1.f / B_);
    const float var = q * (1.f / B_) - m * m;
    const float sc  = gamma[c] / sqrtf(var + EPS_);
    g_scale[c] = sc;
    g_shift[c] = beta[c] - m * sc;
    if (blockIdx.x == 0 && threadIdx.x < E_) g_cnt[threadIdx.x] = 0;
}

// ---------------- routing: warp per row, BN fused into load ----------------
__global__ __launch_bounds__(256)
void mlnn_routing(const float* __restrict__ h,
                  const float* __restrict__ W,    // [H,E]
                  const float* __restrict__ b)    // [E]
{
    __shared__ float Wt[E_ * H_];
    const int tid = threadIdx.x;
    for (int i = tid; i < H_ * E_; i += 256) {
        const int k = i >> 3, e = i & 7;
        Wt[e * H_ + k] = W[i];
    }
    __syncthreads();
    const int warp = tid >> 5, lane = tid & 31;
    const int row  = blockIdx.x * 8 + warp;
    const float* hr = h + (size_t)row * H_;
    float acc[E_] = {};
#pragma unroll
    for (int i = 0; i < H_ / 32; i++) {
        const int k = i * 32 + lane;
        const float hv = fmaf(hr[k], g_scale[k], g_shift[k]);
#pragma unroll
        for (int e = 0; e < E_; e++) acc[e] += hv * Wt[e * H_ + k];
    }
#pragma unroll
    for (int e = 0; e < E_; e++)
#pragma unroll
        for (int off = 16; off; off >>= 1)
            acc[e] += __shfl_xor_sync(0xffffffffu, acc[e], off);
    if (lane == 0) {
        float best = acc[0] + b[0];
        int bi = 0;
#pragma unroll
        for (int e = 1; e < E_; e++) {
            const float v = acc[e] + b[e];
            if (v > best) { best = v; bi = e; }
        }
        g_act[row] = bi;
        atomicAdd(&g_cnt[bi], 1);
    }
}

__global__ void mlnn_scan()
{
    if (threadIdx.x == 0) {
        int s = 0;
#pragma unroll
        for (int e = 0; e < E_; e++) { g_off[e] = s; g_pos[e] = s; s += g_cnt[e]; }
    }
}

__global__ void mlnn_scatter()
{
    const int r = blockIdx.x * 256 + threadIdx.x;
    const int a = g_act[r];
    const int p = atomicAdd(&g_pos[a], 1);
    g_perm[p] = r;
}

// ---------------- launch ----------------
extern "C" void kernel_launch(void* const* d_in, const int* in_sizes, int n_in,
                              void* d_out, int out_size)
{
    const float* x     = (const float*)d_in[0];
    const float* dqn_W = (const float*)d_in[1];
    const float* dqn_b = (const float*)d_in[2];
    const float* Ws    = (const float*)d_in[3];
    const float* bs    = (const float*)d_in[4];
    const float* g0    = (const float*)d_in[5];
    const float* b0    = (const float*)d_in[6];
    const float* We    = (const float*)d_in[7];
    const float* be    = (const float*)d_in[8];
    const float* gmid  = (const float*)d_in[9];
    const float* bmid  = (const float*)d_in[10];
    const float* Wend  = (const float*)d_in[11];
    const float* bend  = (const float*)d_in[12];
    float* out = (float*)d_out;

    float *h, *y, *scl, *shf;
    cudaGetSymbolAddress((void**)&h,   g_h);
    cudaGetSymbolAddress((void**)&y,   g_y);
    cudaGetSymbolAddress((void**)&scl, g_scale);
    cudaGetSymbolAddress((void**)&shf, g_shift);

    cudaFuncSetAttribute(mma_gemm<1024, false, false>,
                         cudaFuncAttributeMaxDynamicSharedMemorySize, SMEM_BYTES);
    cudaFuncSetAttribute(mma_gemm<512, true, true>,
                         cudaFuncAttributeMaxDynamicSharedMemorySize, SMEM_BYTES);
    cudaFuncSetAttribute(mma_gemm<512, false, true>,
                         cudaFuncAttributeMaxDynamicSharedMemorySize, SMEM_BYTES);

    // ---- start layer: h = relu(x @ Ws + bs); BN stats/finalize ----
    mma_gemm<1024, false, false><<<dim3(H_ / 128, B_ / 128), 256, SMEM_BYTES>>>(
        x, Ws, H_, bs, nullptr, nullptr, h, H_);
    mlnn_bn_stats<<<dim3(H_ / 32, 32), dim3(32, 8)>>>(h);
    mlnn_bn_finalize<<<2, 256>>>(g0, b0);

    float* cur = h;
    float* nxt = y;
    for (int l = 0; l < NMID_; l++) {
        mlnn_routing<<<B_ / 8, 256>>>(cur, dqn_W, dqn_b);
        mlnn_scan<<<1, 1>>>();
        mlnn_scatter<<<B_ / 256, 256>>>();
        mma_gemm<512, true, true><<<dim3(H_ / 128, B_ / 128, E_), 256, SMEM_BYTES>>>(
            cur, We + (size_t)l * E_ * H_ * H_, H_,
            be + (size_t)l * E_ * H_, scl, shf, nxt, H_);
        mlnn_bn_stats<<<dim3(H_ / 32, 32), dim3(32, 8)>>>(nxt);
        mlnn_bn_finalize<<<2, 256>>>(gmid + (size_t)l * H_, bmid + (size_t)l * H_);
        float* t = cur; cur = nxt; nxt = t;
    }

    // ---- end layer: out = relu(h @ Wend + bend), BN of last layer fused ----
    mma_gemm<512, false, true><<<dim3(DOUT_ / 128, B_ / 128), 256, SMEM_BYTES>>>(
        cur, Wend, DOUT_, bend, scl, shf, out, DOUT_);
}